// round 16
// baseline (speedup 1.0000x reference)
#include <cuda_runtime.h>
#include <math.h>

#define BB 16
#define HW 65536            // 256*256
#define NPIX (BB*HW)        // 1048576
#define WPR 8               // u32 words per row
#define WPS 2048            // words per sample
#define NWORDS 32768
#define WLCAP 65536

#define TPB 256
#define NB 256              // 16 samples * 16 row-groups (16 rows each)

// ---- device scratch (allocation-free). Reset by finalize each replay. ----
__device__ unsigned g_posbits[NWORDS];
__device__ double g_ce;
__device__ int    g_hard_i, g_t_i, g_inter_i;
__device__ double g_res[BB];
__device__ int    g_haspos[BB];
__device__ int    g_hasneg[BB];
__device__ unsigned g_ticket;
__device__ int    g_wl_n;
__device__ int    g_wl[WLCAP];

__device__ __forceinline__ unsigned smem_u32(const void* p) {
    unsigned a;
    asm("{ .reg .u64 t; cvta.to.shared.u64 t, %1; cvt.u32.u64 %0, t; }" : "=r"(a) : "l"(p));
    return a;
}

#define MBAR_WAIT0(addr) do {                                              \
    unsigned _done;                                                        \
    asm volatile(                                                          \
        "{\n\t.reg .pred p;\n\t"                                           \
        "mbarrier.try_wait.parity.acquire.cta.shared::cta.b64 p, [%1], 0;\n\t" \
        "selp.b32 %0, 1, 0, p;\n\t}"                                       \
        : "=r"(_done) : "r"(addr) : "memory");                             \
    if (!_done) {                                                          \
        asm volatile(                                                      \
            "{\n\t.reg .pred P1;\n\t"                                      \
            "WL_%=:\n\t"                                                   \
            "mbarrier.try_wait.parity.acquire.cta.shared::cta.b64 P1, [%0], 0, 0x989680;\n\t" \
            "@P1 bra.uni WD_%=;\n\t"                                       \
            "bra.uni WL_%=;\n\t"                                           \
            "WD_%=:\n\t}"                                                  \
            :: "r"(addr) : "memory");                                      \
    }                                                                      \
} while (0)

// ---------------------------------------------------------------------------
// Exact fallback (rare; runs in the single finalize block only)
// ---------------------------------------------------------------------------
__device__ __forceinline__ int row_mindx(const unsigned* __restrict__ row, int j, unsigned inv) {
    int wj = j >> 5, off = j & 31;
    int best = 30000;
    unsigned m = (row[wj] ^ inv) >> off;
    if (m) best = __ffs(m) - 1;
    else {
        for (int w = wj + 1; w < WPR; ++w) {
            unsigned x = row[w] ^ inv;
            if (x) { best = 32 * (w - wj) - off + __ffs(x) - 1; break; }
        }
    }
    unsigned ml = (row[wj] ^ inv) << (31 - off);
    if (ml) { int d = __clz(ml); best = min(best, d); }
    else {
        for (int w = wj - 1; w >= 0; --w) {
            unsigned x = row[w] ^ inv;
            if (x) { int d = j - (32 * w + 31 - __clz(x)); best = min(best, d); break; }
        }
    }
    return best;
}

__device__ double fb_contrib(const unsigned* __restrict__ bp, int i, int j, int mybit,
                             int haspos, int hasneg) {
    float d;
    if (!haspos || !hasneg) {
        d = 1.0e9f;                      // reference BIG
    } else {
        unsigned inv = mybit ? 0xffffffffu : 0u;
        int best2 = 1 << 30;
        for (int dy = 0; dy < 256; ++dy) {
            int dy2 = dy * dy;
            if (dy2 >= best2) break;
            int up = i - dy, dn = i + dy;
            if (up >= 0) {
                int dx = row_mindx(bp + up * WPR, j, inv);
                int d2 = dy2 + dx * dx;
                if (d2 < best2) best2 = d2;
            }
            if (dy && dn < 256) {
                int dx = row_mindx(bp + dn * WPR, j, inv);
                int d2 = dy2 + dx * dx;
                if (d2 < best2) best2 = d2;
            }
        }
        d = sqrtf((float)best2);
    }
    return mybit ? -(double)(d - 1.0f) : (double)d;
}

// ---------------------------------------------------------------------------
// Fused: 10 PARALLEL 2-row bulk-async slices (per-warp barriers), warp-local
// waits, shuffle word assembly, block-local 5x5 phase 2, ticket finalize.
// ---------------------------------------------------------------------------
__global__ __launch_bounds__(TPB)
void k_fused(const float* __restrict__ inp, const int* __restrict__ tgt,
             float* __restrict__ out, int out_size) {
    __shared__ __align__(16) float s_c0[20 * 256];   // smem rows 0..19 = abs r0-2..r0+17
    __shared__ __align__(16) float s_c1[20 * 256];
    __shared__ unsigned sh_pw[20 * 8];
    __shared__ unsigned sh_tw[16 * 8];
    __shared__ float sce[8];
    __shared__ int   scnt[8], scnt2[8], sfl[8];
    __shared__ float s_pc[4];
    __shared__ __align__(8) unsigned long long s_mbar[10];
    __shared__ bool  s_last;

    int tid = threadIdx.x, w = tid >> 5, l = tid & 31;
    int s   = blockIdx.x >> 4;           // sample
    int r0  = (blockIdx.x & 15) << 4;    // first of 16 main rows

    // ---------------- 10 parallel 2-row slices ------------------------------
    // slice c<8: smem rows 2c+2,2c+3 (abs r0+2c..r0+2c+1, always valid)
    // slice 8:   smem rows 0,1   (abs r0-2,r0-1; invalid at r0==0)
    // slice 9:   smem rows 18,19 (abs r0+16,r0+17; invalid at r0==240)
    unsigned mb0 = smem_u32(&s_mbar[0]);
    if (tid < 10) {
        asm volatile("mbarrier.init.shared.b64 [%0], %1;"
                     :: "r"(mb0 + tid * 8), "r"(1) : "memory");
    }
    if (tid == 0)
        asm volatile("fence.proxy.async.shared::cta;" ::: "memory");
    __syncthreads();

    if (tid < 10) {
        int c = tid;
        int rr   = (c < 8) ? (2 * c + 2) : ((c == 8) ? 0 : 18);
        int habs = r0 - 2 + rr;
        int valid = (habs >= 0) && (habs + 1 < 256);
        unsigned mb = mb0 + c * 8;
        if (valid) {
            asm volatile("mbarrier.arrive.expect_tx.shared.b64 _, [%0], %1;"
                         :: "r"(mb), "r"(4096u) : "memory");
            const float* b0 = inp + (size_t)(s * 2) * HW + habs * 256;
            unsigned d0 = smem_u32(s_c0) + rr * 1024;
            unsigned d1 = smem_u32(s_c1) + rr * 1024;
            asm volatile("cp.async.bulk.shared::cta.global.mbarrier::complete_tx::bytes [%0], [%1], %2, [%3];"
                         :: "r"(d0), "l"((const char*)b0), "r"(2048u), "r"(mb) : "memory");
            asm volatile("cp.async.bulk.shared::cta.global.mbarrier::complete_tx::bytes [%0], [%1], %2, [%3];"
                         :: "r"(d1), "l"((const char*)(b0 + HW)), "r"(2048u), "r"(mb) : "memory");
        } else {
            // no data: 0-tx arrive flips the barrier immediately
            asm volatile("mbarrier.arrive.expect_tx.shared.b64 _, [%0], %1;"
                         :: "r"(mb), "r"(0u) : "memory");
        }
    }

    // ---------------- targets: 4 LDG.128 issued before any wait ------------
    const int* tb = tgt + (s << 16);
    int4 tv[4];
    #pragma unroll
    for (int q = 0; q < 4; ++q) {
        int f4 = l + 32 * q;
        tv[q] = *(const int4*)(tb + (r0 + 2 * w + (f4 >> 6)) * 256 + (f4 & 63) * 4);
    }

    // wait ONLY for this warp's slice (serviced concurrently with the others)
    MBAR_WAIT0(mb0 + w * 8);

    // ---------------- Phase 1: 16 px/thread, conflict-free LDS -------------
    float ces = 0.0f;
    int hard = 0, tcnt = 0, inter = 0;
    unsigned pall = 0u, pand = 0xFu;

    #pragma unroll
    for (int q = 0; q < 4; ++q) {
        int f4  = l + 32 * q;
        int rr  = 2 * w + 2 + (f4 >> 6);      // smem row
        int c4  = f4 & 63;
        float4 a = *(const float4*)(s_c0 + rr * 256 + c4 * 4);
        float4 c = *(const float4*)(s_c1 + rr * 256 + c4 * 4);
        int4   t = tv[q];

        unsigned pn = 0, hn = 0, tn = 0;
        #define ELEM(E, X0, X1, T) {                                   \
            float x0 = (X0), x1 = (X1); int tt = (T);                  \
            float lse = fmaxf(x0, x1) + __logf(1.0f + __expf(-fabsf(x1 - x0))); \
            ces += lse - ((tt == 1) ? x1 : x0);                        \
            pn |= ((unsigned)(x1 >  x0)) << (E);                       \
            hn |= ((unsigned)(x1 >= x0)) << (E);                       \
            tn |= ((unsigned)(tt == 1))  << (E); }
        ELEM(0, a.x, c.x, t.x)
        ELEM(1, a.y, c.y, t.y)
        ELEM(2, a.z, c.z, t.z)
        ELEM(3, a.w, c.w, t.w)
        #undef ELEM

        hard  += __popc(hn);
        tcnt  += __popc(tn);
        inter += __popc(hn & tn);
        pall  |= pn;
        pand  &= pn;

        // 3-step shuffle assembly within 8-lane groups
        unsigned long long v = (unsigned long long)pn | ((unsigned long long)tn << 32);
        v |= __shfl_xor_sync(0xffffffffu, v, 1) << 4;
        v |= __shfl_xor_sync(0xffffffffu, v, 2) << 8;
        v |= __shfl_xor_sync(0xffffffffu, v, 4) << 16;
        if ((l & 7) == 0) {
            int wl   = 4 * q + (l >> 3);      // 0..15 within warp span
            int mrow = 2 * w + (wl >> 3);     // main row 0..15
            int wc   = wl & 7;
            sh_pw[(mrow + 2) * 8 + wc] = (unsigned)v;
            sh_tw[mrow * 8 + wc]       = (unsigned)(v >> 32);
            g_posbits[s * WPS + (r0 + mrow) * WPR + wc] = (unsigned)v;
        }
    }

    // ---------------- halo: warp0 waits slice 8, warp7 waits slice 9 -------
    if (w == 0 || w == 7) {
        MBAR_WAIT0(mb0 + ((w == 0) ? 8 : 9) * 8);
        int base12 = (w == 0) ? 0 : 18;       // smem rows
        #pragma unroll
        for (int q = 0; q < 4; ++q) {
            int f4 = l + 32 * q;
            int rr = base12 + (f4 >> 6);
            int c4 = f4 & 63;
            int habs = r0 - 2 + rr;
            unsigned pn = 0;
            if (habs >= 0 && habs < 256) {
                float4 a = *(const float4*)(s_c0 + rr * 256 + c4 * 4);
                float4 c = *(const float4*)(s_c1 + rr * 256 + c4 * 4);
                pn |= ((unsigned)(c.x > a.x)) << 0;
                pn |= ((unsigned)(c.y > a.y)) << 1;
                pn |= ((unsigned)(c.z > a.z)) << 2;
                pn |= ((unsigned)(c.w > a.w)) << 3;
            }
            unsigned v = pn;
            v |= __shfl_xor_sync(0xffffffffu, v, 1) << 4;
            v |= __shfl_xor_sync(0xffffffffu, v, 2) << 8;
            v |= __shfl_xor_sync(0xffffffffu, v, 4) << 16;
            if ((l & 7) == 0) {
                int wl = 4 * q + (l >> 3);
                sh_pw[(base12 + (wl >> 3)) * 8 + (wl & 7)] = v;
            }
        }
    }

    // ---------------- reductions -------------------------------------------
    unsigned p1  = ((unsigned)hard << 16) | (unsigned)inter;
    unsigned wp1 = __reduce_add_sync(0xffffffffu, p1);
    unsigned wtc = __reduce_add_sync(0xffffffffu, (unsigned)tcnt);
    unsigned bpos = __ballot_sync(0xffffffffu, pall != 0u);
    unsigned bneg = __ballot_sync(0xffffffffu, pand != 0xFu);
    #pragma unroll
    for (int off = 16; off > 0; off >>= 1)
        ces += __shfl_xor_sync(0xffffffffu, ces, off);
    if (l == 0) {
        sce[w]   = ces;
        scnt[w]  = (int)wp1;
        scnt2[w] = (int)wtc;
        sfl[w]   = (bpos ? 1 : 0) | (bneg ? 2 : 0);
    }
    __syncthreads();

    // ---------------- Phase 2: 5x5 bit-parallel (threads 0..127) -----------
    float contrib = 0.0f;
    if (tid < 128) {
        int wr  = tid >> 3, wc = tid & 7;
        int i   = r0 + wr;
        int i12 = wr + 2;

        unsigned P  = sh_pw[i12 * 8 + wc];
        unsigned T1 = sh_tw[wr * 8 + wc];

        unsigned lm1 = (wc == 0) ? 0xfffffffeu : 0xffffffffu;
        unsigned rm1 = (wc == 7) ? 0x7fffffffu : 0xffffffffu;
        unsigned lm2 = (wc == 0) ? 0xfffffffcu : 0xffffffffu;
        unsigned rm2 = (wc == 7) ? 0x3fffffffu : 0xffffffffu;
        unsigned vu1 = (i >= 1)   ? 0xffffffffu : 0u;
        unsigned vu2 = (i >= 2)   ? 0xffffffffu : 0u;
        unsigned vd1 = (i <= 254) ? 0xffffffffu : 0u;
        unsigned vd2 = (i <= 253) ? 0xffffffffu : 0u;

        #define ROWX(r12, XM, X1L, X1R, X2L, X2R) {                      \
            unsigned Lw = (wc > 0) ? sh_pw[(r12) * 8 + wc - 1] : 0u;     \
            unsigned Mw = sh_pw[(r12) * 8 + wc];                         \
            unsigned Rw = (wc < 7) ? sh_pw[(r12) * 8 + wc + 1] : 0u;     \
            XM  = Mw ^ P;                                                \
            X1L = __funnelshift_l(Lw, Mw, 1) ^ P;                        \
            X1R = __funnelshift_r(Mw, Rw, 1) ^ P;                        \
            X2L = __funnelshift_l(Lw, Mw, 2) ^ P;                        \
            X2R = __funnelshift_r(Mw, Rw, 2) ^ P; }

        unsigned m0, l10, r10, l20, r20;      ROWX(i12,     m0,  l10,  r10,  l20,  r20)
        unsigned mu1, l1u1, r1u1, l2u1, r2u1; ROWX(i12 - 1, mu1, l1u1, r1u1, l2u1, r2u1)
        unsigned md1, l1d1, r1d1, l2d1, r2d1; ROWX(i12 + 1, md1, l1d1, r1d1, l2d1, r2d1)
        unsigned mu2, l1u2, r1u2, l2u2, r2u2; ROWX(i12 - 2, mu2, l1u2, r1u2, l2u2, r2u2)
        unsigned md2, l1d2, r1d2, l2d2, r2d2; ROWX(i12 + 2, md2, l1d2, r1d2, l2d2, r2d2)
        #undef ROWX

        unsigned D1 = (l10 & lm1) | (r10 & rm1) | (mu1 & vu1) | (md1 & vd1);
        unsigned D2 = (((l1u1 & lm1) | (r1u1 & rm1)) & vu1)
                    | (((l1d1 & lm1) | (r1d1 & rm1)) & vd1);
        unsigned D4 = (l20 & lm2) | (r20 & rm2) | (mu2 & vu2) | (md2 & vd2);
        unsigned D5 = (((l2u1 & lm2) | (r2u1 & rm2)) & vu1)
                    | (((l2d1 & lm2) | (r2d1 & rm2)) & vd1)
                    | (((l1u2 & lm1) | (r1u2 & rm1)) & vu2)
                    | (((l1d2 & lm1) | (r1d2 & rm1)) & vd2);
        unsigned D8 = (((l2u2 & lm2) | (r2u2 & rm2)) & vu2)
                    | (((l2d2 & lm2) | (r2d2 & rm2)) & vd2);

        unsigned A1m = D1 & T1;
        unsigned R2m = T1 & ~D1;   unsigned A2m = D2 & R2m;
        unsigned R4m = R2m & ~D2;  unsigned A4m = D4 & R4m;
        unsigned R5m = R4m & ~D4;  unsigned A5m = D5 & R5m;
        unsigned R8m = R5m & ~D5;  unsigned A8m = D8 & R8m;
        unsigned U   = R8m & ~D8;

        const float S2 = 1.41421354f;
        const float S5 = 2.23606801f;
        const float S8 = 2.82842708f;

        contrib  = (float)__popc(A1m & ~P);
        contrib += (float)__popc(A2m & ~P) * S2 - (float)__popc(A2m & P) * (S2 - 1.0f);
        contrib += (float)__popc(A4m & ~P) * 2.0f - (float)__popc(A4m & P) * 1.0f;
        contrib += (float)__popc(A5m & ~P) * S5 - (float)__popc(A5m & P) * (S5 - 1.0f);
        contrib += (float)__popc(A8m & ~P) * S8 - (float)__popc(A8m & P) * (S8 - 1.0f);

        while (U) {   // rare: defer to worklist for the finalize block
            int jb = __ffs(U) - 1; U &= U - 1;
            int j = wc * 32 + jb;
            int mybit = (P >> jb) & 1;
            int slot = atomicAdd(&g_wl_n, 1);
            if (slot < WLCAP)
                g_wl[slot] = (s << 17) | (i << 9) | (j << 1) | mybit;
        }

        #pragma unroll
        for (int off = 16; off > 0; off >>= 1)
            contrib += __shfl_xor_sync(0xffffffffu, contrib, off);
        if (l == 0) s_pc[w] = contrib;
    }
    __syncthreads();

    if (tid == 0) {
        float bce = 0.0f, bpc = 0.0f;
        int bh = 0, bi = 0, bt2 = 0, bfl = 0;
        #pragma unroll
        for (int k = 0; k < 8; ++k) {
            bce += sce[k];
            unsigned c = (unsigned)scnt[k];
            bh += (int)(c >> 16); bi += (int)(c & 0xffffu);
            bt2 += scnt2[k];
            bfl |= sfl[k];
        }
        #pragma unroll
        for (int k = 0; k < 4; ++k) bpc += s_pc[k];
        atomicAdd(&g_ce, (double)bce);
        atomicAdd(&g_hard_i,  bh);
        atomicAdd(&g_t_i,     bt2);
        atomicAdd(&g_inter_i, bi);
        atomicAdd(&g_res[s],  (double)bpc);
        if (bfl & 1) g_haspos[s] = 1;
        if (bfl & 2) g_hasneg[s] = 1;

        __threadfence();
        unsigned tk = atomicAdd(&g_ticket, 1u);
        s_last = (tk == NB - 1);
    }
    __syncthreads();

    // ---------------- Final block: worklist + finalize ----------------------
    if (s_last) {
        if (tid == 0) __threadfence();
        __syncthreads();
        int n = g_wl_n; if (n > WLCAP) n = WLCAP;
        for (int k = tid; k < n; k += TPB) {
            int e = g_wl[k];
            int es = e >> 17, ei = (e >> 9) & 255, ej = (e >> 1) & 255, eb = e & 1;
            double v = fb_contrib(g_posbits + es * WPS, ei, ej, eb,
                                  g_haspos[es], g_hasneg[es]);
            atomicAdd(&g_res[es], v);
        }
        __syncthreads();
        if (tid == 0) {
            double ce = g_ce / (double)NPIX;
            double dice = 1.0 - (2.0 * (double)g_inter_i + 1.0)
                              / ((double)g_hard_i + (double)g_t_i + 1.0);
            double lb = 0.0;
            #pragma unroll
            for (int q = 0; q < BB; ++q)
                if (g_haspos[q]) lb += g_res[q] / (double)HW;
            float r = (float)(ce + dice + lb * lb);
            for (int k = 0; k < out_size; ++k) out[k] = r;

            g_ce = 0.0; g_hard_i = 0; g_t_i = 0; g_inter_i = 0;
            #pragma unroll
            for (int q = 0; q < BB; ++q) { g_res[q] = 0.0; g_haspos[q] = 0; g_hasneg[q] = 0; }
            g_ticket = 0u; g_wl_n = 0;
        }
    }
}

extern "C" void kernel_launch(void* const* d_in, const int* in_sizes, int n_in,
                              void* d_out, int out_size) {
    const float* inputs  = (const float*)d_in[0];   // (16,2,256,256) f32
    const int*   targets = (const int*)  d_in[1];   // (16,256,256)   i32
    k_fused<<<NB, TPB>>>(inputs, targets, (float*)d_out, out_size);
}